// round 3
// baseline (speedup 1.0000x reference)
#include <cuda_runtime.h>

#define NN 100000
#define EE 800000
#define IF 128
#define HH 64

__device__ __constant__ float SCALE_C = 0.70710678118654752440f;
#define BN_EPS 1e-5f

// ---- scratch (device globals; no allocations allowed) ----
__device__ float4 g_h4[NN * (HH / 4)];    // h (in-place across layers), 25.6MB
__device__ float4 g_t4[NN * (HH / 4)];    // t = (h@w)*norm_out, 25.6MB
__device__ float4 g_agg4[NN * (HH / 4)];  // scatter accumulator, 25.6MB
__device__ int   g_dego[NN];
__device__ int   g_degi[NN];
__device__ float g_nout[NN];
__device__ float g_nin[NN];
__device__ float g_sum[HH];
__device__ float g_sumsq[HH];
__device__ float4 g_scale4[HH / 4];
__device__ float4 g_shift4[HH / 4];

// ---------------------------------------------------------------------------
// 1) zero degree counters + BN stats
__global__ void k_zero() {
    int i = blockIdx.x * blockDim.x + threadIdx.x;
    int stride = gridDim.x * blockDim.x;
    for (int j = i; j < NN; j += stride) { g_dego[j] = 0; g_degi[j] = 0; }
    if (i < HH) { g_sum[i] = 0.f; g_sumsq[i] = 0.f; }
}

// 2) degree histogram
__global__ void k_deg(const int* __restrict__ src, const int* __restrict__ dst) {
    int i = blockIdx.x * blockDim.x + threadIdx.x;
    int stride = gridDim.x * blockDim.x;
    for (int e = i; e < EE; e += stride) {
        atomicAdd(&g_dego[src[e]], 1);
        atomicAdd(&g_degi[dst[e]], 1);
    }
}

// 3) normalization factors (clip deg at 1)
__global__ void k_norm() {
    int i = blockIdx.x * blockDim.x + threadIdx.x;
    int stride = gridDim.x * blockDim.x;
    for (int j = i; j < NN; j += stride) {
        int dov = g_dego[j]; if (dov < 1) dov = 1;
        int div = g_degi[j]; if (div < 1) div = 1;
        g_nout[j] = rsqrtf((float)dov);
        g_nin[j]  = rsqrtf((float)div);
    }
}

// ---------------------------------------------------------------------------
// 4) fc: h = x @ fc_w + fc_b   [N,128]@[128,64]
//    one warp per row; lane owns cols (2l, 2l+1); w staged in smem.
__global__ void __launch_bounds__(256) k_fc(const float* __restrict__ x,
                                            const float* __restrict__ w,
                                            const float* __restrict__ b) {
    __shared__ float ws[IF * HH];    // 32KB
    __shared__ float xs[8][IF];      // per-warp row stage, 4KB
    int tid = threadIdx.x;
    for (int i = tid; i < (IF * HH) / 4; i += 256)
        ((float4*)ws)[i] = ((const float4*)w)[i];
    int lane = tid & 31, wid = tid >> 5;
    float2 bias = *(const float2*)&b[2 * lane];
    __syncthreads();

    float* h = (float*)g_h4;
    for (int r = blockIdx.x * 8 + wid; r < NN; r += gridDim.x * 8) {
        ((float4*)xs[wid])[lane] = ((const float4*)(x + (size_t)r * IF))[lane];
        __syncwarp();
        float2 acc = make_float2(0.f, 0.f);
        #pragma unroll 8
        for (int k = 0; k < IF; k++) {
            float xv = xs[wid][k];
            float2 wv = *(float2*)&ws[k * HH + 2 * lane];
            acc.x = fmaf(xv, wv.x, acc.x);
            acc.y = fmaf(xv, wv.y, acc.y);
        }
        acc.x += bias.x; acc.y += bias.y;
        *(float2*)&h[(size_t)r * HH + 2 * lane] = acc;
        __syncwarp();
    }
}

// 5) hidden GEMM: t = (h @ w) * norm_out[row]; also zeroes agg rows
__global__ void __launch_bounds__(256) k_gemm(const float* __restrict__ w) {
    __shared__ float ws[HH * HH];    // 16KB
    __shared__ float xs[8][HH];      // 2KB
    int tid = threadIdx.x;
    for (int i = tid; i < (HH * HH) / 4; i += 256)
        ((float4*)ws)[i] = ((const float4*)w)[i];
    int lane = tid & 31, wid = tid >> 5;
    __syncthreads();

    float* h = (float*)g_h4;
    float* t = (float*)g_t4;
    float* agg = (float*)g_agg4;
    for (int r = blockIdx.x * 8 + wid; r < NN; r += gridDim.x * 8) {
        ((float2*)xs[wid])[lane] = ((const float2*)(h + (size_t)r * HH))[lane];
        __syncwarp();
        float2 acc = make_float2(0.f, 0.f);
        #pragma unroll
        for (int k = 0; k < HH; k++) {
            float xv = xs[wid][k];
            float2 wv = *(float2*)&ws[k * HH + 2 * lane];
            acc.x = fmaf(xv, wv.x, acc.x);
            acc.y = fmaf(xv, wv.y, acc.y);
        }
        float no = g_nout[r];
        acc.x *= no; acc.y *= no;
        *(float2*)&t[(size_t)r * HH + 2 * lane] = acc;
        *(float2*)&agg[(size_t)r * HH + 2 * lane] = make_float2(0.f, 0.f);
        __syncwarp();
    }
}

// 6) edge scatter: agg[dst] += t[src]  — 16 lanes per edge, float4 RED
__global__ void __launch_bounds__(256) k_edge(const int* __restrict__ src,
                                              const int* __restrict__ dst) {
    unsigned g = blockIdx.x * blockDim.x + threadIdx.x;
    unsigned e = g >> 4;
    unsigned l = g & 15;
    if (e >= EE) return;
    int s = src[e], d = dst[e];
    float4 v = g_t4[(size_t)s * (HH / 4) + l];
    atomicAdd(&g_agg4[(size_t)d * (HH / 4) + l], v);
}

// 7) combine: h = (h + agg*norm_in[row] + b) * SCALE   (in place)
__global__ void __launch_bounds__(256) k_combine(const float* __restrict__ b) {
    int i = blockIdx.x * blockDim.x + threadIdx.x;
    int total = NN * (HH / 4);
    if (i >= total) return;
    int row = i >> 4;
    int c4 = i & 15;
    float ni = g_nin[row];
    float4 hv = g_h4[i];
    float4 av = g_agg4[i];
    float4 bv = *(const float4*)&b[c4 * 4];
    float sc = SCALE_C;
    hv.x = (fmaf(av.x, ni, hv.x) + bv.x) * sc;
    hv.y = (fmaf(av.y, ni, hv.y) + bv.y) * sc;
    hv.z = (fmaf(av.z, ni, hv.z) + bv.z) * sc;
    hv.w = (fmaf(av.w, ni, hv.w) + bv.w) * sc;
    g_h4[i] = hv;
}

// 8) BN statistics: per-feature sum and sumsq
__global__ void __launch_bounds__(256) k_bnstats() {
    __shared__ float sh[4][HH];
    __shared__ float sh2[4][HH];
    int tid = threadIdx.x;
    int col = tid & (HH - 1);
    int grp = tid >> 6;               // 0..3
    const float* h = (const float*)g_h4;
    float s = 0.f, s2 = 0.f;
    for (int r = blockIdx.x * 4 + grp; r < NN; r += gridDim.x * 4) {
        float v = h[(size_t)r * HH + col];
        s += v; s2 = fmaf(v, v, s2);
    }
    sh[grp][col] = s; sh2[grp][col] = s2;
    __syncthreads();
    if (grp == 0) {
        s  = sh[0][col] + sh[1][col] + sh[2][col] + sh[3][col];
        s2 = sh2[0][col] + sh2[1][col] + sh2[2][col] + sh2[3][col];
        atomicAdd(&g_sum[col], s);
        atomicAdd(&g_sumsq[col], s2);
    }
}

// 9) BN finalize: scale/shift per feature
__global__ void k_bnfinal(const float* __restrict__ gamma,
                          const float* __restrict__ beta) {
    int c = threadIdx.x;
    if (c >= HH) return;
    float inv_n = 1.0f / (float)NN;
    float mu = g_sum[c] * inv_n;
    float var = g_sumsq[c] * inv_n - mu * mu;
    float istd = rsqrtf(var + BN_EPS);
    float sc = istd * gamma[c];
    ((float*)g_scale4)[c] = sc;
    ((float*)g_shift4)[c] = beta[c] - mu * sc;
}

// 10) BN apply: out = h * scale + shift
__global__ void __launch_bounds__(256) k_bnapply(float4* __restrict__ out) {
    int i = blockIdx.x * blockDim.x + threadIdx.x;
    int total = NN * (HH / 4);
    if (i >= total) return;
    int c4 = i & 15;
    float4 hv = g_h4[i];
    float4 sc = g_scale4[c4];
    float4 sf = g_shift4[c4];
    hv.x = fmaf(hv.x, sc.x, sf.x);
    hv.y = fmaf(hv.y, sc.y, sf.y);
    hv.z = fmaf(hv.z, sc.z, sf.z);
    hv.w = fmaf(hv.w, sc.w, sf.w);
    out[i] = hv;
}

// ---------------------------------------------------------------------------
extern "C" void kernel_launch(void* const* d_in, const int* in_sizes, int n_in,
                              void* d_out, int out_size) {
    const int*   src   = (const int*)d_in[0];
    const int*   dst   = (const int*)d_in[1];
    const float* x     = (const float*)d_in[2];
    const float* fc_w  = (const float*)d_in[3];
    const float* fc_b  = (const float*)d_in[4];
    const float* w1    = (const float*)d_in[5];
    const float* b1    = (const float*)d_in[6];
    const float* w2    = (const float*)d_in[7];
    const float* b2    = (const float*)d_in[8];
    const float* gamma = (const float*)d_in[9];
    const float* beta  = (const float*)d_in[10];
    float4* out = (float4*)d_out;

    const int THREADS = 256;
    const int g_node  = (NN + THREADS - 1) / THREADS;                  // 391
    const int g_edge  = (EE + THREADS - 1) / THREADS;                  // 3125
    const int g_gemm  = 1184;                                         // 148*8
    const int g_scat  = (EE * 16 + THREADS - 1) / THREADS;            // 50000
    const int g_elem  = (NN * (HH / 4) + THREADS - 1) / THREADS;      // 6250
    const int g_stats = 592;

    k_zero<<<g_node, THREADS>>>();
    k_deg<<<g_edge, THREADS>>>(src, dst);
    k_norm<<<g_node, THREADS>>>();

    k_fc<<<g_gemm, THREADS>>>(x, fc_w, fc_b);

    // layer 1
    k_gemm<<<g_gemm, THREADS>>>(w1);
    k_edge<<<g_scat, THREADS>>>(src, dst);
    k_combine<<<g_elem, THREADS>>>(b1);

    // layer 2
    k_gemm<<<g_gemm, THREADS>>>(w2);
    k_edge<<<g_scat, THREADS>>>(src, dst);
    k_combine<<<g_elem, THREADS>>>(b2);

    // batchnorm
    k_bnstats<<<g_stats, THREADS>>>();
    k_bnfinal<<<1, 64>>>(gamma, beta);
    k_bnapply<<<g_elem, THREADS>>>(out);
}

// round 4
// speedup vs baseline: 1.5635x; 1.5635x over previous
#include <cuda_runtime.h>

#define NN 100000
#define EE 800000
#define IF 128
#define HH 64

__device__ __constant__ float SCALE_C = 0.70710678118654752440f;
#define BN_EPS 1e-5f

// ---- scratch (device globals; no allocations allowed) ----
__device__ float4 g_h4[NN * 16];    // h (in-place across layers), 25.6MB
__device__ float4 g_t4[NN * 16];    // t = (h@w)*norm_out, 25.6MB
__device__ float4 g_agg4[NN * 16];  // scatter accumulator, 25.6MB
__device__ int   g_dego[NN];
__device__ int   g_degi[NN];
__device__ float g_nout[NN];
__device__ float g_nin[NN];
__device__ float g_sum[HH];
__device__ float g_sumsq[HH];
__device__ float4 g_scale4[HH / 4];
__device__ float4 g_shift4[HH / 4];

// ---------------------------------------------------------------------------
// 1) zero degree counters + BN stats
__global__ void k_zero() {
    int i = blockIdx.x * blockDim.x + threadIdx.x;
    int stride = gridDim.x * blockDim.x;
    for (int j = i; j < NN; j += stride) { g_dego[j] = 0; g_degi[j] = 0; }
    if (i < HH) { g_sum[i] = 0.f; g_sumsq[i] = 0.f; }
}

// 2) degree histogram
__global__ void k_deg(const int* __restrict__ src, const int* __restrict__ dst) {
    int i = blockIdx.x * blockDim.x + threadIdx.x;
    int stride = gridDim.x * blockDim.x;
    for (int e = i; e < EE; e += stride) {
        atomicAdd(&g_dego[src[e]], 1);
        atomicAdd(&g_degi[dst[e]], 1);
    }
}

// 3) normalization factors (clip deg at 1)
__global__ void k_norm() {
    int i = blockIdx.x * blockDim.x + threadIdx.x;
    int stride = gridDim.x * blockDim.x;
    for (int j = i; j < NN; j += stride) {
        int dov = g_dego[j]; if (dov < 1) dov = 1;
        int div = g_degi[j]; if (div < 1) div = 1;
        g_nout[j] = rsqrtf((float)dov);
        g_nin[j]  = rsqrtf((float)div);
    }
}

// ---------------------------------------------------------------------------
// Register-tiled GEMM: C[NN x 64] = A[NN x K] @ W[K x 64], block = 128 rows,
// thread tile = 8 rows x 4 cols (256 threads as 16x16).
// FC=true : A = x (param),  C = acc + bias       -> g_h4
// FC=false: A = g_h4,       C = acc * nout[row]  -> g_t4, and zero g_agg4
template<int K, bool FC>
__global__ void __launch_bounds__(256) k_mm(const float4* __restrict__ A,
                                            const float4* __restrict__ W,
                                            const float* __restrict__ bias) {
    __shared__ float As[32][128];   // 16KB, transposed chunk: As[k][row]
    __shared__ float Bs[32][64];    //  8KB

    const int tid  = threadIdx.x;
    const int row0 = blockIdx.x * 128;
    const int lrow = tid >> 1;          // 0..127
    const int kq0  = tid & 1;
    const int grow_l = row0 + lrow;
    const bool valid = grow_l < NN;
    const int tx = tid & 15;            // col group (4 cols)
    const int ty = tid >> 4;            // row group (8 rows)

    const float4* Ap = FC ? A : (const float4*)g_h4;

    float acc[8][4];
    #pragma unroll
    for (int r = 0; r < 8; r++)
        #pragma unroll
        for (int c = 0; c < 4; c++) acc[r][c] = 0.f;

    #pragma unroll 1
    for (int ks = 0; ks < K; ks += 32) {
        // load W chunk [32][64] = 512 float4, 2 per thread, coalesced
        #pragma unroll
        for (int i = 0; i < 2; i++) {
            int idx = tid + 256 * i;
            ((float4*)Bs)[idx] = W[(size_t)ks * 16 + idx];
        }
        // load A chunk transposed: rows 0..127, k ks..ks+31
        #pragma unroll
        for (int i = 0; i < 4; i++) {
            int kq = kq0 + 2 * i;       // 0..7 (local quad)
            float4 v = valid ? Ap[(size_t)grow_l * (K / 4) + (ks >> 2) + kq]
                             : make_float4(0.f, 0.f, 0.f, 0.f);
            As[4 * kq + 0][lrow] = v.x;
            As[4 * kq + 1][lrow] = v.y;
            As[4 * kq + 2][lrow] = v.z;
            As[4 * kq + 3][lrow] = v.w;
        }
        __syncthreads();

        #pragma unroll
        for (int k = 0; k < 32; k++) {
            float4 a0 = *(const float4*)&As[k][8 * ty];
            float4 a1 = *(const float4*)&As[k][8 * ty + 4];
            float4 b  = *(const float4*)&Bs[k][4 * tx];
            float av[8] = {a0.x, a0.y, a0.z, a0.w, a1.x, a1.y, a1.z, a1.w};
            float bv[4] = {b.x, b.y, b.z, b.w};
            #pragma unroll
            for (int r = 0; r < 8; r++)
                #pragma unroll
                for (int c = 0; c < 4; c++)
                    acc[r][c] = fmaf(av[r], bv[c], acc[r][c]);
        }
        __syncthreads();
    }

    if (FC) {
        float4 bv = ((const float4*)bias)[tx];
        #pragma unroll
        for (int r = 0; r < 8; r++) {
            int grow = row0 + 8 * ty + r;
            if (grow < NN) {
                float4 o = make_float4(acc[r][0] + bv.x, acc[r][1] + bv.y,
                                       acc[r][2] + bv.z, acc[r][3] + bv.w);
                g_h4[(size_t)grow * 16 + tx] = o;
            }
        }
    } else {
        #pragma unroll
        for (int r = 0; r < 8; r++) {
            int grow = row0 + 8 * ty + r;
            if (grow < NN) {
                float no = g_nout[grow];
                float4 o = make_float4(acc[r][0] * no, acc[r][1] * no,
                                       acc[r][2] * no, acc[r][3] * no);
                g_t4[(size_t)grow * 16 + tx] = o;
                g_agg4[(size_t)grow * 16 + tx] = make_float4(0.f, 0.f, 0.f, 0.f);
            }
        }
    }
}

// ---------------------------------------------------------------------------
// edge scatter: agg[dst] += t[src]  — 16 lanes per edge, float4 RED
__global__ void __launch_bounds__(256) k_edge(const int* __restrict__ src,
                                              const int* __restrict__ dst) {
    unsigned g = blockIdx.x * blockDim.x + threadIdx.x;
    unsigned e = g >> 4;
    unsigned l = g & 15;
    if (e >= EE) return;
    int s = src[e], d = dst[e];
    float4 v = g_t4[(size_t)s * 16 + l];
    atomicAdd(&g_agg4[(size_t)d * 16 + l], v);
}

// ---------------------------------------------------------------------------
// combine: h = (h + agg*norm_in[row] + b) * SCALE   (in place, grid-stride)
// BN=true: also accumulate per-feature sum / sumsq into g_sum / g_sumsq.
template<bool BN>
__global__ void __launch_bounds__(256) k_combine(const float* __restrict__ b) {
    const int c4 = threadIdx.x & 15;
    const float4 bv = ((const float4*)b)[c4];
    const float sc = SCALE_C;
    float4 ls = make_float4(0.f, 0.f, 0.f, 0.f);
    float4 lq = make_float4(0.f, 0.f, 0.f, 0.f);
    const int total = NN * 16;
    for (int i = blockIdx.x * 256 + threadIdx.x; i < total; i += gridDim.x * 256) {
        int row = i >> 4;
        float ni = g_nin[row];
        float4 hv = g_h4[i];
        float4 av = g_agg4[i];
        hv.x = (fmaf(av.x, ni, hv.x) + bv.x) * sc;
        hv.y = (fmaf(av.y, ni, hv.y) + bv.y) * sc;
        hv.z = (fmaf(av.z, ni, hv.z) + bv.z) * sc;
        hv.w = (fmaf(av.w, ni, hv.w) + bv.w) * sc;
        g_h4[i] = hv;
        if (BN) {
            ls.x += hv.x; ls.y += hv.y; ls.z += hv.z; ls.w += hv.w;
            lq.x = fmaf(hv.x, hv.x, lq.x); lq.y = fmaf(hv.y, hv.y, lq.y);
            lq.z = fmaf(hv.z, hv.z, lq.z); lq.w = fmaf(hv.w, hv.w, lq.w);
        }
    }
    if (BN) {
        // lanes l and l^16 share the same c4 -> pairwise reduce
        ls.x += __shfl_xor_sync(0xffffffffu, ls.x, 16);
        ls.y += __shfl_xor_sync(0xffffffffu, ls.y, 16);
        ls.z += __shfl_xor_sync(0xffffffffu, ls.z, 16);
        ls.w += __shfl_xor_sync(0xffffffffu, ls.w, 16);
        lq.x += __shfl_xor_sync(0xffffffffu, lq.x, 16);
        lq.y += __shfl_xor_sync(0xffffffffu, lq.y, 16);
        lq.z += __shfl_xor_sync(0xffffffffu, lq.z, 16);
        lq.w += __shfl_xor_sync(0xffffffffu, lq.w, 16);
        __shared__ float4 ss[8][16];
        __shared__ float4 sq[8][16];
        int lane = threadIdx.x & 31, w = threadIdx.x >> 5;
        if (lane < 16) { ss[w][lane] = ls; sq[w][lane] = lq; }
        __syncthreads();
        if (threadIdx.x < 32) {
            int c = threadIdx.x & 15;
            bool isq = threadIdx.x >= 16;
            float4 t = make_float4(0.f, 0.f, 0.f, 0.f);
            #pragma unroll
            for (int ww = 0; ww < 8; ww++) {
                float4 v = isq ? sq[ww][c] : ss[ww][c];
                t.x += v.x; t.y += v.y; t.z += v.z; t.w += v.w;
            }
            float* dstp = isq ? g_sumsq : g_sum;
            atomicAdd(&dstp[4 * c + 0], t.x);
            atomicAdd(&dstp[4 * c + 1], t.y);
            atomicAdd(&dstp[4 * c + 2], t.z);
            atomicAdd(&dstp[4 * c + 3], t.w);
        }
    }
}

// BN finalize: scale/shift per feature
__global__ void k_bnfinal(const float* __restrict__ gamma,
                          const float* __restrict__ beta) {
    int c = threadIdx.x;
    if (c >= HH) return;
    float inv_n = 1.0f / (float)NN;
    float mu = g_sum[c] * inv_n;
    float var = g_sumsq[c] * inv_n - mu * mu;
    float istd = rsqrtf(var + BN_EPS);
    float sc = istd * gamma[c];
    ((float*)g_scale4)[c] = sc;
    ((float*)g_shift4)[c] = beta[c] - mu * sc;
}

// BN apply: out = h * scale + shift
__global__ void __launch_bounds__(256) k_bnapply(float4* __restrict__ out) {
    int i = blockIdx.x * blockDim.x + threadIdx.x;
    int total = NN * 16;
    if (i >= total) return;
    int c4 = i & 15;
    float4 hv = g_h4[i];
    float4 sc = g_scale4[c4];
    float4 sf = g_shift4[c4];
    hv.x = fmaf(hv.x, sc.x, sf.x);
    hv.y = fmaf(hv.y, sc.y, sf.y);
    hv.z = fmaf(hv.z, sc.z, sf.z);
    hv.w = fmaf(hv.w, sc.w, sf.w);
    out[i] = hv;
}

// ---------------------------------------------------------------------------
extern "C" void kernel_launch(void* const* d_in, const int* in_sizes, int n_in,
                              void* d_out, int out_size) {
    const int*   src   = (const int*)d_in[0];
    const int*   dst   = (const int*)d_in[1];
    const float* x     = (const float*)d_in[2];
    const float* fc_w  = (const float*)d_in[3];
    const float* fc_b  = (const float*)d_in[4];
    const float* w1    = (const float*)d_in[5];
    const float* b1    = (const float*)d_in[6];
    const float* w2    = (const float*)d_in[7];
    const float* b2    = (const float*)d_in[8];
    const float* gamma = (const float*)d_in[9];
    const float* beta  = (const float*)d_in[10];
    float4* out = (float4*)d_out;

    const int THREADS = 256;
    const int g_node  = (NN + THREADS - 1) / THREADS;                  // 391
    const int g_edge  = (EE + THREADS - 1) / THREADS;                  // 3125
    const int g_mm    = (NN + 127) / 128;                              // 782
    const int g_scat  = (EE * 16 + THREADS - 1) / THREADS;             // 50000
    const int g_elem  = (NN * 16 + THREADS - 1) / THREADS;             // 6250
    const int g_comb  = 592;                                           // 148*4

    k_zero<<<g_node, THREADS>>>();
    k_deg<<<g_edge, THREADS>>>(src, dst);
    k_norm<<<g_node, THREADS>>>();

    // fc
    k_mm<IF, true><<<g_mm, THREADS>>>((const float4*)x, (const float4*)fc_w, fc_b);

    // layer 1
    k_mm<HH, false><<<g_mm, THREADS>>>(nullptr, (const float4*)w1, nullptr);
    k_edge<<<g_scat, THREADS>>>(src, dst);
    k_combine<false><<<g_comb, THREADS>>>(b1);

    // layer 2
    k_mm<HH, false><<<g_mm, THREADS>>>(nullptr, (const float4*)w2, nullptr);
    k_edge<<<g_scat, THREADS>>>(src, dst);
    k_combine<true><<<g_comb, THREADS>>>(b2);   // fused BN stats

    // batchnorm
    k_bnfinal<<<1, 64>>>(gamma, beta);
    k_bnapply<<<g_elem, THREADS>>>(out);
}